// round 2
// baseline (speedup 1.0000x reference)
#include <cuda_runtime.h>

// out[n] = prod_f sigmoid(10*(x[n,f]*w[f]+b[f]))^(1/2)
//        = prod_f rsqrt(1 + exp(-10*(x*w+b)))
// Fold: z2 = fma(x, a, c) with a = -10*log2(e)*w, c = -10*log2(e)*b,
//       term = 1 + 2^z2.  Lane partial q = prod of 4 terms (bounded ~6e10),
//       lane value r = rsqrt(q) <= ~1, half-warp butterfly product of r.
//
// One warp handles 2 rows per iteration: lane L loads float4 at
// row_pair*128 + L*4 (128 consecutive floats = rows 2p and 2p+1).
// Lanes 0-15 -> row 2p, lanes 16-31 -> row 2p+1.

#define NEG10LOG2E (-14.4269504088896340736f)  // -10 * log2(e)

__device__ __forceinline__ float ex2(float x) {
    float r;
    asm("ex2.approx.ftz.f32 %0, %1;" : "=f"(r) : "f"(x));
    return r;
}
__device__ __forceinline__ float rsqrt_approx(float x) {
    float r;
    asm("rsqrt.approx.ftz.f32 %0, %1;" : "=f"(r) : "f"(x));
    return r;
}

__global__ void __launch_bounds__(256, 8)
one_to_one_linear_kernel(const float* __restrict__ x,
                         const float* __restrict__ w,
                         const float* __restrict__ b,
                         float* __restrict__ out,
                         int nrows)
{
    const int lane    = threadIdx.x & 31;
    const int warp_g  = (int)((blockIdx.x * blockDim.x + threadIdx.x) >> 5);
    const int nwarps  = (int)((gridDim.x * blockDim.x) >> 5);
    const int col     = (lane * 4) & 63;          // feature column for this lane
    const int half    = lane >> 4;                // 0 -> even row, 1 -> odd row

    // Per-lane feature constants, held in registers for the whole kernel.
    const float4 wv = *reinterpret_cast<const float4*>(w + col);
    const float4 bv = *reinterpret_cast<const float4*>(b + col);
    const float a0 = wv.x * NEG10LOG2E, a1 = wv.y * NEG10LOG2E,
                a2 = wv.z * NEG10LOG2E, a3 = wv.w * NEG10LOG2E;
    const float c0 = bv.x * NEG10LOG2E, c1 = bv.y * NEG10LOG2E,
                c2 = bv.z * NEG10LOG2E, c3 = bv.w * NEG10LOG2E;

    const long long npairs = (long long)(nrows >> 1);

    for (long long p = warp_g; p < npairs; p += nwarps) {
        const float4 xv =
            *reinterpret_cast<const float4*>(x + p * 128 + (lane << 2));

        float e0 = ex2(fmaf(xv.x, a0, c0));
        float e1 = ex2(fmaf(xv.y, a1, c1));
        float e2 = ex2(fmaf(xv.z, a2, c2));
        float e3 = ex2(fmaf(xv.w, a3, c3));

        float q = (1.0f + e0) * (1.0f + e1) * (1.0f + e2) * (1.0f + e3);
        float r = rsqrt_approx(q);      // lane partial, in (0, 1] -> no overflow

        // Product reduction within each 16-lane half (one row per half).
        r *= __shfl_xor_sync(0xffffffffu, r, 1);
        r *= __shfl_xor_sync(0xffffffffu, r, 2);
        r *= __shfl_xor_sync(0xffffffffu, r, 4);
        r *= __shfl_xor_sync(0xffffffffu, r, 8);

        if ((lane & 15) == 0)
            out[p * 2 + half] = r;
    }

    // Odd-row tail (not hit for this problem's N, but keep it correct).
    if ((nrows & 1) && warp_g == 0) {
        const long long row = (long long)nrows - 1;
        if (lane < 16) {
            const float4 xv =
                *reinterpret_cast<const float4*>(x + row * 64 + (lane << 2));
            float e0 = ex2(fmaf(xv.x, a0, c0));
            float e1 = ex2(fmaf(xv.y, a1, c1));
            float e2 = ex2(fmaf(xv.z, a2, c2));
            float e3 = ex2(fmaf(xv.w, a3, c3));
            float q = (1.0f + e0) * (1.0f + e1) * (1.0f + e2) * (1.0f + e3);
            float r = rsqrt_approx(q);
            r *= __shfl_xor_sync(0x0000ffffu, r, 1);
            r *= __shfl_xor_sync(0x0000ffffu, r, 2);
            r *= __shfl_xor_sync(0x0000ffffu, r, 4);
            r *= __shfl_xor_sync(0x0000ffffu, r, 8);
            if (lane == 0) out[row] = r;
        }
    }
}

extern "C" void kernel_launch(void* const* d_in, const int* in_sizes, int n_in,
                              void* d_out, int out_size)
{
    const float* x = (const float*)d_in[0];
    const float* w = (const float*)d_in[1];
    const float* b = (const float*)d_in[2];
    float* out = (float*)d_out;

    const int F = in_sizes[1];            // 64
    const int nrows = in_sizes[0] / F;    // 2097152
    (void)n_in; (void)out_size;

    // 148 SMs * 8 CTAs of 256 threads = full occupancy, exactly 1 wave.
    const int block = 256;
    int grid = 148 * 8;
    const int warps_needed = (nrows + 1) / 2;
    const int grid_needed = (warps_needed + (block / 32) - 1) / (block / 32);
    if (grid > grid_needed) grid = grid_needed;

    one_to_one_linear_kernel<<<grid, block>>>(x, w, b, out, nrows);
}

// round 4
// speedup vs baseline: 1.0028x; 1.0028x over previous
#include <cuda_runtime.h>

// out[n] = prod_f sigmoid(10*(x[n,f]*w[f]+b[f]))^(1/2)
//        = prod_f rsqrt(1 + exp(-10*(x*w+b)))
// Fold: z = fma(x, a, c) with a = -10*log2(e)*w, c = -10*log2(e)*b,
//       term = 1 + 2^z.  Lane partial q = prod of 4 terms (bounded ~6e10),
//       lane value r = rsqrt(q) <= ~1, half-warp butterfly product.
//
// One warp handles 2 rows per row-pair: lane L loads float4 at
// pair*128 + L*4. Lanes 0-15 -> even row, lanes 16-31 -> odd row.
// Loop unrolled x2 with both LDG.128s issued up front (MLP_p1=2) so each
// warp keeps 1KB in flight -> DRAM-throughput-bound instead of latency-bound.

#define NEG10LOG2E (-14.4269504088896340736f)  // -10 * log2(e)

__device__ __forceinline__ float ex2(float x) {
    float r;
    asm("ex2.approx.ftz.f32 %0, %1;" : "=f"(r) : "f"(x));
    return r;
}
__device__ __forceinline__ float rsqrt_approx(float x) {
    float r;
    asm("rsqrt.approx.ftz.f32 %0, %1;" : "=f"(r) : "f"(x));
    return r;
}

struct LaneConsts {
    float a0, a1, a2, a3, c0, c1, c2, c3;
};

__device__ __forceinline__ float row_partial(const float4& xv, const LaneConsts& k) {
    float e0 = ex2(fmaf(xv.x, k.a0, k.c0));
    float e1 = ex2(fmaf(xv.y, k.a1, k.c1));
    float e2 = ex2(fmaf(xv.z, k.a2, k.c2));
    float e3 = ex2(fmaf(xv.w, k.a3, k.c3));
    float q = (1.0f + e0) * (1.0f + e1) * (1.0f + e2) * (1.0f + e3);
    return rsqrt_approx(q);          // in (0, 1] -> butterfly product never overflows
}

__device__ __forceinline__ float butterfly16(float r) {
    r *= __shfl_xor_sync(0xffffffffu, r, 1);
    r *= __shfl_xor_sync(0xffffffffu, r, 2);
    r *= __shfl_xor_sync(0xffffffffu, r, 4);
    r *= __shfl_xor_sync(0xffffffffu, r, 8);
    return r;
}

__global__ void __launch_bounds__(256, 6)
one_to_one_linear_kernel(const float* __restrict__ x,
                         const float* __restrict__ w,
                         const float* __restrict__ b,
                         float* __restrict__ out,
                         int nrows)
{
    const int lane    = threadIdx.x & 31;
    const int warp_g  = (int)((blockIdx.x * blockDim.x + threadIdx.x) >> 5);
    const int nwarps  = (int)((gridDim.x * blockDim.x) >> 5);
    const int col     = (lane * 4) & 63;          // feature column for this lane
    const int half    = lane >> 4;                // 0 -> even row, 1 -> odd row

    LaneConsts k;
    {
        const float4 wv = *reinterpret_cast<const float4*>(w + col);
        const float4 bv = *reinterpret_cast<const float4*>(b + col);
        k.a0 = wv.x * NEG10LOG2E; k.a1 = wv.y * NEG10LOG2E;
        k.a2 = wv.z * NEG10LOG2E; k.a3 = wv.w * NEG10LOG2E;
        k.c0 = bv.x * NEG10LOG2E; k.c1 = bv.y * NEG10LOG2E;
        k.c2 = bv.z * NEG10LOG2E; k.c3 = bv.w * NEG10LOG2E;
    }

    const long long npairs  = (long long)(nrows >> 1);
    const long long stride  = nwarps;
    const long long stride2 = 2 * stride;
    const int       loff    = lane << 2;

    long long p = warp_g;
    for (; p + stride < npairs; p += stride2) {
        // Issue both independent 128-bit loads before any compute.
        const float4 xa = __ldcs(reinterpret_cast<const float4*>(x + p * 128 + loff));
        const float4 xb = __ldcs(reinterpret_cast<const float4*>(x + (p + stride) * 128 + loff));

        float ra = row_partial(xa, k);
        float rb = row_partial(xb, k);

        ra = butterfly16(ra);
        rb = butterfly16(rb);

        if ((lane & 15) == 0) {
            out[p * 2 + half]                = ra;
            out[(p + stride) * 2 + half]     = rb;
        }
    }
    if (p < npairs) {
        const float4 xa = __ldcs(reinterpret_cast<const float4*>(x + p * 128 + loff));
        float ra = butterfly16(row_partial(xa, k));
        if ((lane & 15) == 0)
            out[p * 2 + half] = ra;
    }

    // Odd-row tail (not hit for this problem's N, but keep it correct).
    if ((nrows & 1) && warp_g == 0) {
        const long long row = (long long)nrows - 1;
        if (lane < 16) {
            const float4 xv = *reinterpret_cast<const float4*>(x + row * 64 + loff);
            float r = row_partial(xv, k);
            r *= __shfl_xor_sync(0x0000ffffu, r, 1);
            r *= __shfl_xor_sync(0x0000ffffu, r, 2);
            r *= __shfl_xor_sync(0x0000ffffu, r, 4);
            r *= __shfl_xor_sync(0x0000ffffu, r, 8);
            if (lane == 0) out[row] = r;
        }
    }
}

extern "C" void kernel_launch(void* const* d_in, const int* in_sizes, int n_in,
                              void* d_out, int out_size)
{
    const float* x = (const float*)d_in[0];
    const float* w = (const float*)d_in[1];
    const float* b = (const float*)d_in[2];
    float* out = (float*)d_out;

    const int F = in_sizes[1];            // 64
    const int nrows = in_sizes[0] / F;    // 2097152
    (void)n_in; (void)out_size;

    // 148 SMs * 6 CTAs of 256 threads (relaxed reg budget for the x2 unroll).
    const int block = 256;
    int grid = 148 * 6;
    const int warps_needed = (nrows + 1) / 2;
    const int grid_needed = (warps_needed + (block / 32) - 1) / (block / 32);
    if (grid > grid_needed) grid = grid_needed;

    one_to_one_linear_kernel<<<grid, block>>>(x, w, b, out, nrows);
}